// round 16
// baseline (speedup 1.0000x reference)
#include <cuda_runtime.h>
#include <cuda_bf16.h>
#include <cuda_fp16.h>
#include <math.h>
#include <stdint.h>

#define NPIX 4096
#define CDIM 256
#define CBAR 32
#define BATCH 8

// ---- scratch (device globals; no runtime allocation) ----
__device__ float g_l[BATCH * NPIX];
__device__ float g_invl[BATCH * NPIX];
__device__ __nv_bfloat16 g_xfh[BATCH * NPIX * CBAR];           // [b][n][c] hi
__device__ __nv_bfloat16 g_xfl[BATCH * NPIX * CBAR];
__device__ __nv_bfloat16 g_xgh[BATCH * NPIX * CBAR];
__device__ __nv_bfloat16 g_xgl[BATCH * NPIX * CBAR];
__device__ __nv_bfloat16 g_whh[CDIM * CDIM];                   // Wh hi [o][c]
__device__ __nv_bfloat16 g_whl[CDIM * CDIM];
__device__ __nv_bfloat16 g_xth[BATCH * NPIX * CDIM];           // x^T hi [b][n][c]
__device__ __nv_bfloat16 g_xtl[BATCH * NPIX * CDIM];
__device__ __nv_bfloat16 g_ph[(size_t)BATCH * NPIX * NPIX];    // 256 MB: bf16(exp(S^T)) [b][j][i]
__device__ __half g_xh16[BATCH * CDIM * NPIX];                 // fp16(xh) [b][c][i]

// ---- base-ISA helpers (sm_80+) ----
__device__ __forceinline__ uint32_t smem_u32(const void* p) {
    uint32_t a;
    asm("{ .reg .u64 t; cvta.to.shared.u64 t, %1; cvt.u32.u64 %0, t; }" : "=r"(a) : "l"(p));
    return a;
}
#define CPASYNC16(d, s) asm volatile("cp.async.cg.shared.global [%0], [%1], 16;" :: "r"(d), "l"(s) : "memory")
#define CPCOMMIT()      asm volatile("cp.async.commit_group;" ::: "memory")
#define CPWAIT(n)       asm volatile("cp.async.wait_group %0;" :: "n"(n) : "memory")

__device__ __forceinline__ void ldmx4(uint32_t* r, uint32_t addr) {
    asm volatile("ldmatrix.sync.aligned.m8n8.x4.shared.b16 {%0,%1,%2,%3}, [%4];"
                 : "=r"(r[0]), "=r"(r[1]), "=r"(r[2]), "=r"(r[3]) : "r"(addr));
}
__device__ __forceinline__ void mma16816(float* d, const uint32_t* a, const uint32_t* b) {
    asm volatile("mma.sync.aligned.m16n8k16.row.col.f32.bf16.bf16.f32 "
                 "{%0,%1,%2,%3}, {%4,%5,%6,%7}, {%8,%9}, {%0,%1,%2,%3};"
                 : "+f"(d[0]), "+f"(d[1]), "+f"(d[2]), "+f"(d[3])
                 : "r"(a[0]), "r"(a[1]), "r"(a[2]), "r"(a[3]), "r"(b[0]), "r"(b[1]));
}
__device__ __forceinline__ void mma16816h(float* d, const uint32_t* a, const uint32_t* b) {
    asm volatile("mma.sync.aligned.m16n8k16.row.col.f32.f16.f16.f32 "
                 "{%0,%1,%2,%3}, {%4,%5,%6,%7}, {%8,%9}, {%0,%1,%2,%3};"
                 : "+f"(d[0]), "+f"(d[1]), "+f"(d[2]), "+f"(d[3])
                 : "r"(a[0]), "r"(a[1]), "r"(a[2]), "r"(a[3]), "r"(b[0]), "r"(b[1]));
}
__device__ __forceinline__ void pack_hilo(float v, __nv_bfloat16* hi, __nv_bfloat16* lo) {
    __nv_bfloat16 h = __float2bfloat16(v);
    *hi = h;
    *lo = __float2bfloat16(v - __bfloat162float(h));
}

// ============================================================================
// Kernel 0: setup — zero l AND convert Wh -> bf16 hi/lo, one launch.
// ============================================================================
__global__ __launch_bounds__(256) void setup_kernel(const float* __restrict__ W)
{
    int id = blockIdx.x * 256 + threadIdx.x;
    if (id < BATCH * NPIX) {
        g_l[id] = 0.0f;
    } else {
        int idx = (id - BATCH * NPIX) * 4;
        float4 w = *(const float4*)(W + idx);
        ushort4 h4, l4;
        float v[4] = {w.x, w.y, w.z, w.w};
        #pragma unroll
        for (int q = 0; q < 4; q++) {
            __nv_bfloat16 h, l;
            pack_hilo(v[q], &h, &l);
            ((unsigned short*)&h4)[q] = __bfloat16_as_ushort(h);
            ((unsigned short*)&l4)[q] = __bfloat16_as_ushort(l);
        }
        *(ushort4*)(g_whh + idx) = h4;
        *(ushort4*)(g_whl + idx) = l4;
    }
}

// ============================================================================
// Kernel 1: FUSED f+g projections + x transpose-convert (unchanged R15).
// ============================================================================
__global__ __launch_bounds__(256) void proj_fg_kernel(
    const float* __restrict__ Wf, const float* __restrict__ bf,
    const float* __restrict__ Wg, const float* __restrict__ bg,
    const float* __restrict__ x)
{
    __shared__ float Ws[64][33];
    __shared__ float Xs[32][132];

    const int b  = blockIdx.z;
    const int n0 = blockIdx.x * 128;
    const int t  = threadIdx.x;
    const int tx = t & 31;
    const int ty = t >> 5;

    const float* xb = x + (size_t)b * CDIM * NPIX;

    float af[4][4] = {};
    float ag[4][4] = {};

    for (int k0 = 0; k0 < CDIM; k0 += 32) {
        #pragma unroll
        for (int q = 0; q < 2; q++) {
            int id = t + q * 256;
            int row = id >> 3, c4 = (id & 7) << 2;
            const float* src = (row < 32) ? (Wf + (size_t)row * CDIM)
                                          : (Wg + (size_t)(row - 32) * CDIM);
            float4 w4 = *(const float4*)(src + k0 + c4);
            Ws[row][c4 + 0] = w4.x; Ws[row][c4 + 1] = w4.y;
            Ws[row][c4 + 2] = w4.z; Ws[row][c4 + 3] = w4.w;
        }
        #pragma unroll
        for (int p = 0; p < 4; p++) {
            int idx = t + p * 256;
            int r = idx >> 5, c4 = (idx & 31) << 2;
            *(float4*)&Xs[r][c4] = *(const float4*)(xb + (size_t)(k0 + r) * NPIX + n0 + c4);
        }
        __syncthreads();

        #pragma unroll
        for (int k = 0; k < 32; k++) {
            float4 bv = *(float4*)&Xs[k][tx * 4];
            #pragma unroll
            for (int i = 0; i < 4; i++) {
                float wf = Ws[ty * 4 + i][k];
                float wg = Ws[32 + ty * 4 + i][k];
                af[i][0] += wf * bv.x; af[i][1] += wf * bv.y; af[i][2] += wf * bv.z; af[i][3] += wf * bv.w;
                ag[i][0] += wg * bv.x; ag[i][1] += wg * bv.y; ag[i][2] += wg * bv.z; ag[i][3] += wg * bv.w;
            }
        }

        #pragma unroll
        for (int p = 0; p < 4; p++) {
            int idx = t + p * 256;
            int n = idx & 127, cg = idx >> 7;
            ushort4 h4, l4;
            #pragma unroll
            for (int j = 0; j < 4; j++) {
                __nv_bfloat16 h, l;
                pack_hilo(Xs[cg * 4 + j][n], &h, &l);
                ((unsigned short*)&h4)[j] = __bfloat16_as_ushort(h);
                ((unsigned short*)&l4)[j] = __bfloat16_as_ushort(l);
            }
            size_t off = ((size_t)b * NPIX + n0 + n) * CDIM + k0 + cg * 4;
            *(ushort4*)(g_xth + off) = h4;
            *(ushort4*)(g_xtl + off) = l4;
        }
        __syncthreads();
    }

    float bbf[4], bbg[4];
    #pragma unroll
    for (int i = 0; i < 4; i++) { bbf[i] = bf[ty * 4 + i]; bbg[i] = bg[ty * 4 + i]; }
    #pragma unroll
    for (int j = 0; j < 4; j++) {
        int n = n0 + tx * 4 + j;
        ushort4 fh4, fl4, gh4, gl4;
        #pragma unroll
        for (int i = 0; i < 4; i++) {
            __nv_bfloat16 h, l;
            pack_hilo(af[i][j] + bbf[i], &h, &l);
            ((unsigned short*)&fh4)[i] = __bfloat16_as_ushort(h);
            ((unsigned short*)&fl4)[i] = __bfloat16_as_ushort(l);
            pack_hilo(ag[i][j] + bbg[i], &h, &l);
            ((unsigned short*)&gh4)[i] = __bfloat16_as_ushort(h);
            ((unsigned short*)&gl4)[i] = __bfloat16_as_ushort(l);
        }
        size_t off = ((size_t)b * NPIX + n) * CBAR + ty * 4;
        *(ushort4*)(g_xfh + off) = fh4;
        *(ushort4*)(g_xfl + off) = fl4;
        *(ushort4*)(g_xgh + off) = gh4;
        *(ushort4*)(g_xgl + off) = gl4;
    }
}

// ============================================================================
// Kernel 1b: h-projection on tensor cores (unchanged; validated).
// ============================================================================
#define PROWB 80
#define P_AL 10240
#define P_BH 20480
#define P_BL 40960
#define PSTAGE 61440

__global__ __launch_bounds__(512, 1) void proj_tc_kernel(const float* __restrict__ bias)
{
    extern __shared__ char smem[];
    const uint32_t sb = smem_u32(smem);

    const int b  = blockIdx.z;
    const int m0 = blockIdx.y * 128;
    const int n0 = blockIdx.x * 256;
    const int t  = threadIdx.x;
    const int warp = t >> 5, lane = t & 31;
    const int wm = (warp & 3) * 32;
    const int wn = (warp >> 2) * 64;

    const __nv_bfloat16* bth = g_xth + (size_t)b * NPIX * CDIM;
    const __nv_bfloat16* btl = g_xtl + (size_t)b * NPIX * CDIM;

    float acc[2][8][4];
    #pragma unroll
    for (int i = 0; i < 2; i++)
        #pragma unroll
        for (int j = 0; j < 8; j++)
            #pragma unroll
            for (int q = 0; q < 4; q++) acc[i][j][q] = 0.f;

    const int a_row = lane & 15, a_k16 = (lane >> 4) << 4;
    const int b_row = (lane & 7) + ((lane >> 4) & 1) * 8;
    const int b_k16 = ((lane >> 3) & 1) * 16;

    const int NCH = CDIM / 32;

    auto issue = [&](int ck, int s) {
        const uint32_t st = sb + s * PSTAGE;
        const int k0 = ck * 32;
        {
            int r = t >> 2, g = t & 3;
            const __nv_bfloat16* sh = g_whh + (size_t)(m0 + r) * CDIM + k0 + g * 8;
            const __nv_bfloat16* sl = g_whl + (size_t)(m0 + r) * CDIM + k0 + g * 8;
            uint32_t d = st + r * PROWB + g * 16;
            CPASYNC16(d, sh);
            CPASYNC16(d + P_AL, sl);
        }
        #pragma unroll
        for (int q = 0; q < 2; q++) {
            int id = t + q * 512;
            int r = id >> 2, g = id & 3;
            const __nv_bfloat16* sh = bth + (size_t)(n0 + r) * CDIM + k0 + g * 8;
            const __nv_bfloat16* sl = btl + (size_t)(n0 + r) * CDIM + k0 + g * 8;
            uint32_t d = st + r * PROWB + g * 16;
            CPASYNC16(d + P_BH, sh);
            CPASYNC16(d + P_BL, sl);
        }
        CPCOMMIT();
    };

    issue(0, 0);
    for (int ck = 0; ck < NCH; ck++) {
        const int s = ck & 1;
        if (ck + 1 < NCH) { issue(ck + 1, s ^ 1); CPWAIT(1); }
        else              { CPWAIT(0); }
        __syncthreads();

        const uint32_t st = sb + s * PSTAGE;
        #pragma unroll
        for (int ks = 0; ks < 2; ks++) {
            const int kB = ks * 32;
            uint32_t a_h[2][4], a_l[2][4];
            #pragma unroll
            for (int ms = 0; ms < 2; ms++) {
                uint32_t ra = st + (wm + ms * 16 + a_row) * PROWB + kB + a_k16;
                ldmx4(a_h[ms], ra);
                ldmx4(a_l[ms], ra + P_AL);
            }
            #pragma unroll
            for (int np = 0; np < 4; np++) {
                uint32_t rb = st + (wn + np * 16 + b_row) * PROWB + kB + b_k16;
                uint32_t b_h[4], b_l[4];
                ldmx4(b_h, rb + P_BH);
                ldmx4(b_l, rb + P_BL);
                #pragma unroll
                for (int ms = 0; ms < 2; ms++) {
                    #pragma unroll
                    for (int nh = 0; nh < 2; nh++) {
                        float* d = acc[ms][np * 2 + nh];
                        mma16816(d, a_h[ms], b_h + 2 * nh);
                        mma16816(d, a_h[ms], b_l + 2 * nh);
                        mma16816(d, a_l[ms], b_h + 2 * nh);
                    }
                }
            }
        }
        __syncthreads();
    }

    const int jq = lane >> 2, cq = (lane & 3) * 2;
    #pragma unroll
    for (int ms = 0; ms < 2; ms++) {
        int o0r = m0 + wm + ms * 16 + jq;
        float b0 = bias[o0r], b1 = bias[o0r + 8];
        __half* row0 = g_xh16 + ((size_t)b * CDIM + o0r) * NPIX;
        __half* row1 = g_xh16 + ((size_t)b * CDIM + o0r + 8) * NPIX;
        #pragma unroll
        for (int ni = 0; ni < 8; ni++) {
            int n = n0 + wn + ni * 8 + cq;
            float* a4 = acc[ms][ni];
            __half h00 = __float2half_rn(a4[0] + b0);
            __half h01 = __float2half_rn(a4[1] + b0);
            __half h10 = __float2half_rn(a4[2] + b1);
            __half h11 = __float2half_rn(a4[3] + b1);
            *(uint32_t*)(row0 + n) = ((uint32_t)__half_as_ushort(h01) << 16) | __half_as_ushort(h00);
            *(uint32_t*)(row1 + n) = ((uint32_t)__half_as_ushort(h11) << 16) | __half_as_ushort(h10);
        }
    }
}

// ============================================================================
// Kernel 2b: scores, BM=256, 512 threads, 128 CTAs -> SINGLE WAVE.
// A (xg) 256 rows hi + 256 lo resident; B (xf) 128-i tiles double-buffered.
// 16 warps = 4 m-groups (64 j) x 4 n-groups (32 i).
// smem: A 40960 + 2 B-stages 40960 + pstage 69632 = 151552 B.
// ============================================================================
#define SROWB 80
#define S3A_BYTES 40960
#define S3A_LO 20480
#define S3B_LO 10240
#define S3B_STAGE 20480
#define S3PST_OFF (S3A_BYTES + 2 * S3B_STAGE)    // 81920
#define PST_ROWB 272
#define SCORE_SMEM (S3PST_OFF + 256 * PST_ROWB)  // 151552

__global__ __launch_bounds__(512, 1) void score_kernel()
{
    extern __shared__ char smem[];
    const uint32_t sa = smem_u32(smem);
    const uint32_t sb0 = sa + S3A_BYTES;
    char* pst = smem + S3PST_OFF;

    const int b  = blockIdx.y;
    const int j0 = blockIdx.x * 256;
    const int t  = threadIdx.x;
    const int warp = t >> 5, lane = t & 31;
    const int mbase = (warp & 3) * 64;
    const int wn = (warp >> 2) * 32;

    const __nv_bfloat16* xfh = g_xfh + (size_t)b * NPIX * CBAR;
    const __nv_bfloat16* xfl = g_xfl + (size_t)b * NPIX * CBAR;
    const __nv_bfloat16* xgh = g_xgh + (size_t)b * NPIX * CBAR;
    const __nv_bfloat16* xgl = g_xgl + (size_t)b * NPIX * CBAR;
    __nv_bfloat16* ph = g_ph + (size_t)b * NPIX * NPIX;
    float* lrow = g_l + b * NPIX;

    // A: 512 rows (256 hi + 256 lo) x 64B -> 2048 tasks, 4/thread
    #pragma unroll
    for (int q = 0; q < 4; q++) {
        int id = t + q * 512;
        int r = id >> 2, g16 = id & 3;
        const __nv_bfloat16* src = ((r < 256) ? xgh : xgl) + ((size_t)(j0 + (r & 255))) * CBAR + g16 * 8;
        CPASYNC16(sa + r * SROWB + g16 * 16, src);
    }
    // B iter 0: 256 rows -> 1024 tasks, 2/thread
    #pragma unroll
    for (int q = 0; q < 2; q++) {
        int id = t + q * 512;
        int r = id >> 2, g16 = id & 3;
        const __nv_bfloat16* src = ((r < 128) ? xfh : xfl) + ((size_t)(r & 127)) * CBAR + g16 * 8;
        CPASYNC16(sb0 + r * SROWB + g16 * 16, src);
    }
    CPCOMMIT();

    const int a_row = lane & 15, a_k16 = (lane >> 4) << 4;
    const int b_row = (lane & 7) + ((lane >> 4) & 1) * 8;
    const int b_k16 = ((lane >> 3) & 1) * 16;

    const int NIT = NPIX / 128;

    for (int it = 0; it < NIT; it++) {
        const int s = it & 1;
        if (it + 1 < NIT) {
            const int i0n = (it + 1) * 128;
            const uint32_t st = sb0 + (s ^ 1) * S3B_STAGE;
            #pragma unroll
            for (int q = 0; q < 2; q++) {
                int id = t + q * 512;
                int r = id >> 2, g16 = id & 3;
                const __nv_bfloat16* src = ((r < 128) ? xfh : xfl) + ((size_t)(i0n + (r & 127))) * CBAR + g16 * 8;
                CPASYNC16(st + r * SROWB + g16 * 16, src);
            }
            CPCOMMIT();
            CPWAIT(1);
        } else {
            CPWAIT(0);
        }
        __syncthreads();

        const uint32_t stg = sb0 + s * S3B_STAGE;
        float sacc[4][4][4];
        #pragma unroll
        for (int m = 0; m < 4; m++)
            #pragma unroll
            for (int n = 0; n < 4; n++)
                #pragma unroll
                for (int q = 0; q < 4; q++) sacc[m][n][q] = 0.f;

        #pragma unroll
        for (int ks = 0; ks < 2; ks++) {
            const int kB = ks * 32;
            uint32_t a_h[4][4], a_l[4][4];
            #pragma unroll
            for (int ms = 0; ms < 4; ms++) {
                uint32_t ra = sa + (mbase + ms * 16 + a_row) * SROWB + kB + a_k16;
                ldmx4(a_h[ms], ra);
                ldmx4(a_l[ms], ra + S3A_LO);
            }
            #pragma unroll
            for (int np = 0; np < 2; np++) {
                uint32_t rb = stg + (wn + np * 16 + b_row) * SROWB + kB + b_k16;
                uint32_t b_h[4], b_l[4];
                ldmx4(b_h, rb);
                ldmx4(b_l, rb + S3B_LO);
                #pragma unroll
                for (int ms = 0; ms < 4; ms++) {
                    #pragma unroll
                    for (int nh = 0; nh < 2; nh++) {
                        float* d = sacc[ms][np * 2 + nh];
                        mma16816(d, a_h[ms], b_h + 2 * nh);
                        mma16816(d, a_h[ms], b_l + 2 * nh);
                        mma16816(d, a_l[ms], b_h + 2 * nh);
                    }
                }
            }
        }

        const int i0 = it * 128;
        #pragma unroll
        for (int nn = 0; nn < 4; nn++) {
            const int icl = wn + nn * 8 + (lane & 3) * 2;
            float cs0 = 0.f, cs1 = 0.f;
            #pragma unroll
            for (int ms = 0; ms < 4; ms++) {
                float* d = sacc[ms][nn];
                float p0 = __expf(d[0]);
                float p1 = __expf(d[1]);
                float p2 = __expf(d[2]);
                float p3 = __expf(d[3]);
                cs0 += p0 + p2; cs1 += p1 + p3;
                const int jl = mbase + ms * 16 + (lane >> 2);
                uint32_t pk01 = ((uint32_t)__bfloat16_as_ushort(__float2bfloat16(p1)) << 16)
                              |  (uint32_t)__bfloat16_as_ushort(__float2bfloat16(p0));
                uint32_t pk23 = ((uint32_t)__bfloat16_as_ushort(__float2bfloat16(p3)) << 16)
                              |  (uint32_t)__bfloat16_as_ushort(__float2bfloat16(p2));
                *(uint32_t*)(pst + jl * PST_ROWB + icl * 2)       = pk01;
                *(uint32_t*)(pst + (jl + 8) * PST_ROWB + icl * 2) = pk23;
            }
            #pragma unroll
            for (int off = 4; off <= 16; off <<= 1) {
                cs0 += __shfl_xor_sync(0xffffffffu, cs0, off);
                cs1 += __shfl_xor_sync(0xffffffffu, cs1, off);
            }
            if (lane < 4) {
                atomicAdd(lrow + i0 + icl, cs0);
                atomicAdd(lrow + i0 + icl + 1, cs1);
            }
        }
        __syncthreads();

        // coalesced store: 256 rows x 256B = 4096 tasks, 8/thread
        #pragma unroll
        for (int q = 0; q < 8; q++) {
            int id = q * 512 + t;
            int jl = id >> 4, w16 = id & 15;
            uint4 v = *(uint4*)(pst + jl * PST_ROWB + w16 * 16);
            *(uint4*)(ph + (size_t)(j0 + jl) * NPIX + i0 + w16 * 8) = v;
        }
        __syncthreads();
    }
}

// ============================================================================
// Kernel 2c: finalize.  invl = 1/l.
// ============================================================================
__global__ __launch_bounds__(256) void finalize_kernel()
{
    int idx = blockIdx.x * blockDim.x + threadIdx.x;
    if (idx < BATCH * NPIX) g_invl[idx] = 1.0f / g_l[idx];
}

// ============================================================================
// Kernel 3: output GEMM, fp16 mma, beta fused into A-path, BK=64
// (unchanged R14/R15; validated, at MMA floor).
// ============================================================================
#define ROWB2 144
#define G_OFF_A 0
#define G_OFF_B 18432
#define G_STAGE 55296
#define G_INVL (2 * G_STAGE)
#define GEMM_SMEM (G_INVL + NPIX * 4)

__global__ __launch_bounds__(512, 1) void out_gemm_mma(
    const float* __restrict__ x, const float* __restrict__ gamma,
    float* __restrict__ out)
{
    extern __shared__ char smem[];
    const uint32_t sb = smem_u32(smem);
    float* sinvl = (float*)(smem + G_INVL);

    const int b  = blockIdx.y;
    const int m0 = blockIdx.x * 128;
    const int t  = threadIdx.x;
    const int warp = t >> 5, lane = t & 31;
    const int wm = (warp & 3) * 32;
    const int wn = (warp >> 2) * 64;

    const __nv_bfloat16* pb = g_ph + (size_t)b * NPIX * NPIX;
    const __half* xh = g_xh16 + (size_t)b * CDIM * NPIX;
    const float* invl = g_invl + b * NPIX;

    float acc[2][8][4];
    #pragma unroll
    for (int i = 0; i < 2; i++)
        #pragma unroll
        for (int j = 0; j < 8; j++)
            #pragma unroll
            for (int q = 0; q < 4; q++) acc[i][j][q] = 0.f;

    const int a_row = lane & 15, a_k16 = (lane >> 4) << 4;
    const int b_row = (lane & 7) + ((lane >> 4) & 1) * 8;
    const int b_k16 = ((lane >> 3) & 1) * 16;

    const int NCH = NPIX / 64;

    const int ar0 = t >> 3, ag0 = t & 7;
    const int ar1 = (t + 512) >> 3, ag1 = (t + 512) & 7;

    auto convA = [&](uint4* areg, int i0, uint32_t st) {
        #pragma unroll
        for (int q = 0; q < 2; q++) {
            int r = q ? ar1 : ar0, g = q ? ag1 : ag0;
            const uint32_t* aw = (const uint32_t*)&areg[q];
            float iv[8];
            #pragma unroll
            for (int k = 0; k < 8; k++) iv[k] = sinvl[i0 + g * 8 + k];
            uint32_t w[4];
            #pragma unroll
            for (int p = 0; p < 4; p++) {
                float lo = __bfloat162float(__ushort_as_bfloat16((unsigned short)(aw[p] & 0xFFFF)));
                float hi = __bfloat162float(__ushort_as_bfloat16((unsigned short)(aw[p] >> 16)));
                __half h0 = __float2half_rn(lo * iv[p * 2]);
                __half h1 = __float2half_rn(hi * iv[p * 2 + 1]);
                w[p] = ((uint32_t)__half_as_ushort(h1) << 16) | (uint32_t)__half_as_ushort(h0);
            }
            *(uint4*)((char*)smem + (st - smem_u32(smem)) + r * ROWB2 + g * 16 + G_OFF_A) = *(uint4*)w;
        }
    };

    {
        int vi = t * 8;
        *(float4*)(sinvl + vi)     = *(const float4*)(invl + vi);
        *(float4*)(sinvl + vi + 4) = *(const float4*)(invl + vi + 4);
    }
    uint4 areg[2];
    areg[0] = *(const uint4*)(pb + (size_t)(m0 + ar0) * NPIX + ag0 * 8);
    areg[1] = *(const uint4*)(pb + (size_t)(m0 + ar1) * NPIX + ag1 * 8);
    {
        const uint32_t st = sb;
        #pragma unroll
        for (int q = 0; q < 4; q++) {
            int id = t + q * 512;
            int r = id >> 3, g = id & 7;
            CPASYNC16(st + r * ROWB2 + g * 16 + G_OFF_B, xh + (size_t)r * NPIX + g * 8);
        }
        CPCOMMIT();
    }
    __syncthreads();
    convA(areg, 0, sb);

    for (int kt = 0; kt < NCH; kt++) {
        const int s = kt & 1;
        const int i0n = (kt + 1) * 64;
        if (kt + 1 < NCH) {
            areg[0] = *(const uint4*)(pb + (size_t)(m0 + ar0) * NPIX + i0n + ag0 * 8);
            areg[1] = *(const uint4*)(pb + (size_t)(m0 + ar1) * NPIX + i0n + ag1 * 8);
            const uint32_t st = sb + (s ^ 1) * G_STAGE;
            #pragma unroll
            for (int q = 0; q < 4; q++) {
                int id = t + q * 512;
                int r = id >> 3, g = id & 7;
                CPASYNC16(st + r * ROWB2 + g * 16 + G_OFF_B, xh + (size_t)r * NPIX + i0n + g * 8);
            }
            CPCOMMIT();
            CPWAIT(1);
        } else {
            CPWAIT(0);
        }
        __syncthreads();

        const uint32_t st = sb + s * G_STAGE;
        #pragma unroll
        for (int ks = 0; ks < 4; ks++) {
            const int kB = ks * 32;
            uint32_t a_f[2][4];
            #pragma unroll
            for (int ms = 0; ms < 2; ms++) {
                uint32_t ra = st + (wm + ms * 16 + a_row) * ROWB2 + kB + a_k16;
                ldmx4(a_f[ms], ra + G_OFF_A);
            }
            #pragma unroll
            for (int np = 0; np < 4; np++) {
                uint32_t rb = st + (wn + np * 16 + b_row) * ROWB2 + kB + b_k16;
                uint32_t b_f[4];
                ldmx4(b_f, rb + G_OFF_B);
                #pragma unroll
                for (int ms = 0; ms < 2; ms++) {
                    #pragma unroll
                    for (int nh = 0; nh < 2; nh++) {
                        mma16816h(acc[ms][np * 2 + nh], a_f[ms], b_f + 2 * nh);
                    }
                }
            }
        }

        if (kt + 1 < NCH) {
            convA(areg, i0n, sb + (s ^ 1) * G_STAGE);
        }
        __syncthreads();
    }

    const float g = gamma[0];
    const float* xb = x   + (size_t)b * CDIM * NPIX;
    float*       ob = out + (size_t)b * CDIM * NPIX;
    const int jq = lane >> 2, cq = (lane & 3) * 2;

    #pragma unroll
    for (int ms = 0; ms < 2; ms++) {
        #pragma unroll
        for (int ni = 0; ni < 8; ni++) {
            int j = m0 + wm + ms * 16 + jq;
            int c = wn + ni * 8 + cq;
            float* a4 = acc[ms][ni];
            ob[(size_t)c * NPIX + j]            = xb[(size_t)c * NPIX + j]            + g * a4[0];
            ob[(size_t)(c + 1) * NPIX + j]      = xb[(size_t)(c + 1) * NPIX + j]      + g * a4[1];
            ob[(size_t)c * NPIX + j + 8]        = xb[(size_t)c * NPIX + j + 8]        + g * a4[2];
            ob[(size_t)(c + 1) * NPIX + j + 8]  = xb[(size_t)(c + 1) * NPIX + j + 8]  + g * a4[3];
        }
    }
}

// ============================================================================
extern "C" void kernel_launch(void* const* d_in, const int* in_sizes, int n_in,
                              void* d_out, int out_size)
{
    const float* x     = (const float*)d_in[0];
    const float* Wf    = (const float*)d_in[1];
    const float* bf    = (const float*)d_in[2];
    const float* Wg    = (const float*)d_in[3];
    const float* bg    = (const float*)d_in[4];
    const float* Wh    = (const float*)d_in[5];
    const float* bh    = (const float*)d_in[6];
    const float* gamma = (const float*)d_in[7];
    float* out = (float*)d_out;

    (void)in_sizes; (void)n_in; (void)out_size;

    cudaFuncSetAttribute(out_gemm_mma, cudaFuncAttributeMaxDynamicSharedMemorySize,
                         GEMM_SMEM);
    cudaFuncSetAttribute(score_kernel, cudaFuncAttributeMaxDynamicSharedMemorySize,
                         SCORE_SMEM);
    cudaFuncSetAttribute(proj_tc_kernel, cudaFuncAttributeMaxDynamicSharedMemorySize,
                         2 * PSTAGE);

    dim3 blk(256);
    setup_kernel<<<(BATCH * NPIX + CDIM * CDIM / 4 + 255) / 256, blk>>>(Wh);
    proj_fg_kernel<<<dim3(NPIX / 128, 1, BATCH), blk>>>(Wf, bf, Wg, bg, x);
    proj_tc_kernel<<<dim3(NPIX / 256, CDIM / 128, BATCH), 512, 2 * PSTAGE>>>(bh);
    score_kernel<<<dim3(NPIX / 256, BATCH), 512, SCORE_SMEM>>>();
    finalize_kernel<<<(BATCH * NPIX + 255) / 256, blk>>>();
    out_gemm_mma<<<dim3(NPIX / 128, BATCH), 512, GEMM_SMEM>>>(x, gamma, out);
}

// round 17
// speedup vs baseline: 1.1357x; 1.1357x over previous
#include <cuda_runtime.h>
#include <cuda_bf16.h>
#include <cuda_fp16.h>
#include <math.h>
#include <stdint.h>

#define NPIX 4096
#define CDIM 256
#define CBAR 32
#define BATCH 8

// ---- scratch (device globals; no runtime allocation) ----
__device__ float g_l[BATCH * NPIX];
__device__ float g_invl[BATCH * NPIX];
__device__ __nv_bfloat16 g_xfh[BATCH * NPIX * CBAR];           // [b][n][c] hi
__device__ __nv_bfloat16 g_xfl[BATCH * NPIX * CBAR];
__device__ __nv_bfloat16 g_xgh[BATCH * NPIX * CBAR];
__device__ __nv_bfloat16 g_xgl[BATCH * NPIX * CBAR];
__device__ __nv_bfloat16 g_whh[CDIM * CDIM];                   // Wh hi [o][c]
__device__ __nv_bfloat16 g_whl[CDIM * CDIM];
__device__ __nv_bfloat16 g_xth[BATCH * NPIX * CDIM];           // x^T hi [b][n][c]
__device__ __nv_bfloat16 g_xtl[BATCH * NPIX * CDIM];
__device__ __nv_bfloat16 g_ph[(size_t)BATCH * NPIX * NPIX];    // 256 MB: bf16(exp(S^T)) [b][j][i]
__device__ __half g_xh16[BATCH * CDIM * NPIX];                 // fp16(xh) [b][c][i]

// ---- base-ISA helpers (sm_80+) ----
__device__ __forceinline__ uint32_t smem_u32(const void* p) {
    uint32_t a;
    asm("{ .reg .u64 t; cvta.to.shared.u64 t, %1; cvt.u32.u64 %0, t; }" : "=r"(a) : "l"(p));
    return a;
}
#define CPASYNC16(d, s) asm volatile("cp.async.cg.shared.global [%0], [%1], 16;" :: "r"(d), "l"(s) : "memory")
#define CPCOMMIT()      asm volatile("cp.async.commit_group;" ::: "memory")
#define CPWAIT(n)       asm volatile("cp.async.wait_group %0;" :: "n"(n) : "memory")

__device__ __forceinline__ void ldmx4(uint32_t* r, uint32_t addr) {
    asm volatile("ldmatrix.sync.aligned.m8n8.x4.shared.b16 {%0,%1,%2,%3}, [%4];"
                 : "=r"(r[0]), "=r"(r[1]), "=r"(r[2]), "=r"(r[3]) : "r"(addr));
}
__device__ __forceinline__ void mma16816(float* d, const uint32_t* a, const uint32_t* b) {
    asm volatile("mma.sync.aligned.m16n8k16.row.col.f32.bf16.bf16.f32 "
                 "{%0,%1,%2,%3}, {%4,%5,%6,%7}, {%8,%9}, {%0,%1,%2,%3};"
                 : "+f"(d[0]), "+f"(d[1]), "+f"(d[2]), "+f"(d[3])
                 : "r"(a[0]), "r"(a[1]), "r"(a[2]), "r"(a[3]), "r"(b[0]), "r"(b[1]));
}
__device__ __forceinline__ void mma16816h(float* d, const uint32_t* a, const uint32_t* b) {
    asm volatile("mma.sync.aligned.m16n8k16.row.col.f32.f16.f16.f32 "
                 "{%0,%1,%2,%3}, {%4,%5,%6,%7}, {%8,%9}, {%0,%1,%2,%3};"
                 : "+f"(d[0]), "+f"(d[1]), "+f"(d[2]), "+f"(d[3])
                 : "r"(a[0]), "r"(a[1]), "r"(a[2]), "r"(a[3]), "r"(b[0]), "r"(b[1]));
}
__device__ __forceinline__ void pack_hilo(float v, __nv_bfloat16* hi, __nv_bfloat16* lo) {
    __nv_bfloat16 h = __float2bfloat16(v);
    *hi = h;
    *lo = __float2bfloat16(v - __bfloat162float(h));
}
// one-instruction pack of two floats (round-nearest-even, bit-identical to
// __float2bfloat16/__float2half_rn pairs)
__device__ __forceinline__ uint32_t cvt_bf16x2(float hi, float lo) {
    uint32_t d;
    asm("cvt.rn.bf16x2.f32 %0, %1, %2;" : "=r"(d) : "f"(hi), "f"(lo));
    return d;
}
__device__ __forceinline__ uint32_t cvt_f16x2(float hi, float lo) {
    uint32_t d;
    asm("cvt.rn.f16x2.f32 %0, %1, %2;" : "=r"(d) : "f"(hi), "f"(lo));
    return d;
}

// ============================================================================
// Kernel 0: setup — zero l AND convert Wh -> bf16 hi/lo, one launch.
// ============================================================================
__global__ __launch_bounds__(256) void setup_kernel(const float* __restrict__ W)
{
    int id = blockIdx.x * 256 + threadIdx.x;
    if (id < BATCH * NPIX) {
        g_l[id] = 0.0f;
    } else {
        int idx = (id - BATCH * NPIX) * 4;
        float4 w = *(const float4*)(W + idx);
        ushort4 h4, l4;
        float v[4] = {w.x, w.y, w.z, w.w};
        #pragma unroll
        for (int q = 0; q < 4; q++) {
            __nv_bfloat16 h, l;
            pack_hilo(v[q], &h, &l);
            ((unsigned short*)&h4)[q] = __bfloat16_as_ushort(h);
            ((unsigned short*)&l4)[q] = __bfloat16_as_ushort(l);
        }
        *(ushort4*)(g_whh + idx) = h4;
        *(ushort4*)(g_whl + idx) = l4;
    }
}

// ============================================================================
// Kernel 1: FUSED f+g projections + x transpose-convert (unchanged R15).
// ============================================================================
__global__ __launch_bounds__(256) void proj_fg_kernel(
    const float* __restrict__ Wf, const float* __restrict__ bf,
    const float* __restrict__ Wg, const float* __restrict__ bg,
    const float* __restrict__ x)
{
    __shared__ float Ws[64][33];
    __shared__ float Xs[32][132];

    const int b  = blockIdx.z;
    const int n0 = blockIdx.x * 128;
    const int t  = threadIdx.x;
    const int tx = t & 31;
    const int ty = t >> 5;

    const float* xb = x + (size_t)b * CDIM * NPIX;

    float af[4][4] = {};
    float ag[4][4] = {};

    for (int k0 = 0; k0 < CDIM; k0 += 32) {
        #pragma unroll
        for (int q = 0; q < 2; q++) {
            int id = t + q * 256;
            int row = id >> 3, c4 = (id & 7) << 2;
            const float* src = (row < 32) ? (Wf + (size_t)row * CDIM)
                                          : (Wg + (size_t)(row - 32) * CDIM);
            float4 w4 = *(const float4*)(src + k0 + c4);
            Ws[row][c4 + 0] = w4.x; Ws[row][c4 + 1] = w4.y;
            Ws[row][c4 + 2] = w4.z; Ws[row][c4 + 3] = w4.w;
        }
        #pragma unroll
        for (int p = 0; p < 4; p++) {
            int idx = t + p * 256;
            int r = idx >> 5, c4 = (idx & 31) << 2;
            *(float4*)&Xs[r][c4] = *(const float4*)(xb + (size_t)(k0 + r) * NPIX + n0 + c4);
        }
        __syncthreads();

        #pragma unroll
        for (int k = 0; k < 32; k++) {
            float4 bv = *(float4*)&Xs[k][tx * 4];
            #pragma unroll
            for (int i = 0; i < 4; i++) {
                float wf = Ws[ty * 4 + i][k];
                float wg = Ws[32 + ty * 4 + i][k];
                af[i][0] += wf * bv.x; af[i][1] += wf * bv.y; af[i][2] += wf * bv.z; af[i][3] += wf * bv.w;
                ag[i][0] += wg * bv.x; ag[i][1] += wg * bv.y; ag[i][2] += wg * bv.z; ag[i][3] += wg * bv.w;
            }
        }

        #pragma unroll
        for (int p = 0; p < 4; p++) {
            int idx = t + p * 256;
            int n = idx & 127, cg = idx >> 7;
            ushort4 h4, l4;
            #pragma unroll
            for (int j = 0; j < 4; j++) {
                __nv_bfloat16 h, l;
                pack_hilo(Xs[cg * 4 + j][n], &h, &l);
                ((unsigned short*)&h4)[j] = __bfloat16_as_ushort(h);
                ((unsigned short*)&l4)[j] = __bfloat16_as_ushort(l);
            }
            size_t off = ((size_t)b * NPIX + n0 + n) * CDIM + k0 + cg * 4;
            *(ushort4*)(g_xth + off) = h4;
            *(ushort4*)(g_xtl + off) = l4;
        }
        __syncthreads();
    }

    float bbf[4], bbg[4];
    #pragma unroll
    for (int i = 0; i < 4; i++) { bbf[i] = bf[ty * 4 + i]; bbg[i] = bg[ty * 4 + i]; }
    #pragma unroll
    for (int j = 0; j < 4; j++) {
        int n = n0 + tx * 4 + j;
        ushort4 fh4, fl4, gh4, gl4;
        #pragma unroll
        for (int i = 0; i < 4; i++) {
            __nv_bfloat16 h, l;
            pack_hilo(af[i][j] + bbf[i], &h, &l);
            ((unsigned short*)&fh4)[i] = __bfloat16_as_ushort(h);
            ((unsigned short*)&fl4)[i] = __bfloat16_as_ushort(l);
            pack_hilo(ag[i][j] + bbg[i], &h, &l);
            ((unsigned short*)&gh4)[i] = __bfloat16_as_ushort(h);
            ((unsigned short*)&gl4)[i] = __bfloat16_as_ushort(l);
        }
        size_t off = ((size_t)b * NPIX + n) * CBAR + ty * 4;
        *(ushort4*)(g_xfh + off) = fh4;
        *(ushort4*)(g_xfl + off) = fl4;
        *(ushort4*)(g_xgh + off) = gh4;
        *(ushort4*)(g_xgl + off) = gl4;
    }
}

// ============================================================================
// Kernel 1b: h-projection on tensor cores (R13 core; f16x2 pack epilogue).
// ============================================================================
#define PROWB 80
#define P_AL 10240
#define P_BH 20480
#define P_BL 40960
#define PSTAGE 61440

__global__ __launch_bounds__(512, 1) void proj_tc_kernel(const float* __restrict__ bias)
{
    extern __shared__ char smem[];
    const uint32_t sb = smem_u32(smem);

    const int b  = blockIdx.z;
    const int m0 = blockIdx.y * 128;
    const int n0 = blockIdx.x * 256;
    const int t  = threadIdx.x;
    const int warp = t >> 5, lane = t & 31;
    const int wm = (warp & 3) * 32;
    const int wn = (warp >> 2) * 64;

    const __nv_bfloat16* bth = g_xth + (size_t)b * NPIX * CDIM;
    const __nv_bfloat16* btl = g_xtl + (size_t)b * NPIX * CDIM;

    float acc[2][8][4];
    #pragma unroll
    for (int i = 0; i < 2; i++)
        #pragma unroll
        for (int j = 0; j < 8; j++)
            #pragma unroll
            for (int q = 0; q < 4; q++) acc[i][j][q] = 0.f;

    const int a_row = lane & 15, a_k16 = (lane >> 4) << 4;
    const int b_row = (lane & 7) + ((lane >> 4) & 1) * 8;
    const int b_k16 = ((lane >> 3) & 1) * 16;

    const int NCH = CDIM / 32;

    auto issue = [&](int ck, int s) {
        const uint32_t st = sb + s * PSTAGE;
        const int k0 = ck * 32;
        {
            int r = t >> 2, g = t & 3;
            const __nv_bfloat16* sh = g_whh + (size_t)(m0 + r) * CDIM + k0 + g * 8;
            const __nv_bfloat16* sl = g_whl + (size_t)(m0 + r) * CDIM + k0 + g * 8;
            uint32_t d = st + r * PROWB + g * 16;
            CPASYNC16(d, sh);
            CPASYNC16(d + P_AL, sl);
        }
        #pragma unroll
        for (int q = 0; q < 2; q++) {
            int id = t + q * 512;
            int r = id >> 2, g = id & 3;
            const __nv_bfloat16* sh = bth + (size_t)(n0 + r) * CDIM + k0 + g * 8;
            const __nv_bfloat16* sl = btl + (size_t)(n0 + r) * CDIM + k0 + g * 8;
            uint32_t d = st + r * PROWB + g * 16;
            CPASYNC16(d + P_BH, sh);
            CPASYNC16(d + P_BL, sl);
        }
        CPCOMMIT();
    };

    issue(0, 0);
    for (int ck = 0; ck < NCH; ck++) {
        const int s = ck & 1;
        if (ck + 1 < NCH) { issue(ck + 1, s ^ 1); CPWAIT(1); }
        else              { CPWAIT(0); }
        __syncthreads();

        const uint32_t st = sb + s * PSTAGE;
        #pragma unroll
        for (int ks = 0; ks < 2; ks++) {
            const int kB = ks * 32;
            uint32_t a_h[2][4], a_l[2][4];
            #pragma unroll
            for (int ms = 0; ms < 2; ms++) {
                uint32_t ra = st + (wm + ms * 16 + a_row) * PROWB + kB + a_k16;
                ldmx4(a_h[ms], ra);
                ldmx4(a_l[ms], ra + P_AL);
            }
            #pragma unroll
            for (int np = 0; np < 4; np++) {
                uint32_t rb = st + (wn + np * 16 + b_row) * PROWB + kB + b_k16;
                uint32_t b_h[4], b_l[4];
                ldmx4(b_h, rb + P_BH);
                ldmx4(b_l, rb + P_BL);
                #pragma unroll
                for (int ms = 0; ms < 2; ms++) {
                    #pragma unroll
                    for (int nh = 0; nh < 2; nh++) {
                        float* d = acc[ms][np * 2 + nh];
                        mma16816(d, a_h[ms], b_h + 2 * nh);
                        mma16816(d, a_h[ms], b_l + 2 * nh);
                        mma16816(d, a_l[ms], b_h + 2 * nh);
                    }
                }
            }
        }
        __syncthreads();
    }

    const int jq = lane >> 2, cq = (lane & 3) * 2;
    #pragma unroll
    for (int ms = 0; ms < 2; ms++) {
        int o0r = m0 + wm + ms * 16 + jq;
        float b0 = bias[o0r], b1 = bias[o0r + 8];
        __half* row0 = g_xh16 + ((size_t)b * CDIM + o0r) * NPIX;
        __half* row1 = g_xh16 + ((size_t)b * CDIM + o0r + 8) * NPIX;
        #pragma unroll
        for (int ni = 0; ni < 8; ni++) {
            int n = n0 + wn + ni * 8 + cq;
            float* a4 = acc[ms][ni];
            *(uint32_t*)(row0 + n) = cvt_f16x2(a4[1] + b0, a4[0] + b0);
            *(uint32_t*)(row1 + n) = cvt_f16x2(a4[3] + b1, a4[2] + b1);
        }
    }
}

// ============================================================================
// Kernel 2b: scores — REVERTED to R15 shape (BM=128, 256 thr, occ 2;
// inter-CTA overlap hides the epilogue).  Changes vs R15:
//   * cvt.rn.bf16x2.f32 single-instruction packing (bit-identical)
//   * trailing per-iter __syncthreads removed (ordering covered by the
//     post-CPWAIT sync before the next epilogue's pst writes)
// ============================================================================
#define SROWB 80
#define S2A_BYTES 20480
#define S2A_LO 10240
#define S2B_LO 10240
#define S2B_STAGE 20480
#define S2PST_OFF (S2A_BYTES + 2 * S2B_STAGE)
#define PST_ROWB 272
#define SCORE_SMEM (S2PST_OFF + 128 * PST_ROWB)

__global__ __launch_bounds__(256, 2) void score_kernel()
{
    extern __shared__ char smem[];
    const uint32_t sa = smem_u32(smem);
    const uint32_t sb0 = sa + S2A_BYTES;
    char* pst = smem + S2PST_OFF;

    const int b  = blockIdx.y;
    const int j0 = blockIdx.x * 128;
    const int t  = threadIdx.x;
    const int warp = t >> 5, lane = t & 31;
    const int mbase = (warp & 1) * 64;
    const int wn = (warp >> 1) * 32;

    const __nv_bfloat16* xfh = g_xfh + (size_t)b * NPIX * CBAR;
    const __nv_bfloat16* xfl = g_xfl + (size_t)b * NPIX * CBAR;
    const __nv_bfloat16* xgh = g_xgh + (size_t)b * NPIX * CBAR;
    const __nv_bfloat16* xgl = g_xgl + (size_t)b * NPIX * CBAR;
    __nv_bfloat16* ph = g_ph + (size_t)b * NPIX * NPIX;
    float* lrow = g_l + b * NPIX;

    #pragma unroll
    for (int q = 0; q < 4; q++) {
        int id = t + q * 256;
        int r = id >> 2, g16 = id & 3;
        const __nv_bfloat16* src = ((r < 128) ? xgh : xgl) + ((size_t)(j0 + (r & 127))) * CBAR + g16 * 8;
        CPASYNC16(sa + r * SROWB + g16 * 16, src);
    }
    #pragma unroll
    for (int q = 0; q < 4; q++) {
        int id = t + q * 256;
        int r = id >> 2, g16 = id & 3;
        const __nv_bfloat16* src = ((r < 128) ? xfh : xfl) + ((size_t)(r & 127)) * CBAR + g16 * 8;
        CPASYNC16(sb0 + r * SROWB + g16 * 16, src);
    }
    CPCOMMIT();

    const int a_row = lane & 15, a_k16 = (lane >> 4) << 4;
    const int b_row = (lane & 7) + ((lane >> 4) & 1) * 8;
    const int b_k16 = ((lane >> 3) & 1) * 16;

    const int NIT = NPIX / 128;

    for (int it = 0; it < NIT; it++) {
        const int s = it & 1;
        if (it + 1 < NIT) {
            const int i0n = (it + 1) * 128;
            const uint32_t st = sb0 + (s ^ 1) * S2B_STAGE;
            #pragma unroll
            for (int q = 0; q < 4; q++) {
                int id = t + q * 256;
                int r = id >> 2, g16 = id & 3;
                const __nv_bfloat16* src = ((r < 128) ? xfh : xfl) + ((size_t)(i0n + (r & 127))) * CBAR + g16 * 8;
                CPASYNC16(st + r * SROWB + g16 * 16, src);
            }
            CPCOMMIT();
            CPWAIT(1);
        } else {
            CPWAIT(0);
        }
        __syncthreads();   // B stage ready; also orders prior pst reads vs new writes

        const uint32_t stg = sb0 + s * S2B_STAGE;
        float sacc[4][4][4];
        #pragma unroll
        for (int m = 0; m < 4; m++)
            #pragma unroll
            for (int n = 0; n < 4; n++)
                #pragma unroll
                for (int q = 0; q < 4; q++) sacc[m][n][q] = 0.f;

        #pragma unroll
        for (int ks = 0; ks < 2; ks++) {
            const int kB = ks * 32;
            uint32_t a_h[4][4], a_l[4][4];
            #pragma unroll
            for (int ms = 0; ms < 4; ms++) {
                uint32_t ra = sa + (mbase + ms * 16 + a_row) * SROWB + kB + a_k16;
                ldmx4(a_h[ms], ra);
                ldmx4(a_l[ms], ra + S2A_LO);
            }
            #pragma unroll
            for (int np = 0; np < 2; np++) {
                uint32_t rb = stg + (wn + np * 16 + b_row) * SROWB + kB + b_k16;
                uint32_t b_h[4], b_l[4];
                ldmx4(b_h, rb);
                ldmx4(b_l, rb + S2B_LO);
                #pragma unroll
                for (int ms = 0; ms < 4; ms++) {
                    #pragma unroll
                    for (int nh = 0; nh < 2; nh++) {
                        float* d = sacc[ms][np * 2 + nh];
                        mma16816(d, a_h[ms], b_h + 2 * nh);
                        mma16816(d, a_h[ms], b_l + 2 * nh);
                        mma16816(d, a_l[ms], b_h + 2 * nh);
                    }
                }
            }
        }

        const int i0 = it * 128;
        #pragma unroll
        for (int nn = 0; nn < 4; nn++) {
            const int icl = wn + nn * 8 + (lane & 3) * 2;
            float cs0 = 0.f, cs1 = 0.f;
            #pragma unroll
            for (int ms = 0; ms < 4; ms++) {
                float* d = sacc[ms][nn];
                float p0 = __expf(d[0]);
                float p1 = __expf(d[1]);
                float p2 = __expf(d[2]);
                float p3 = __expf(d[3]);
                cs0 += p0 + p2; cs1 += p1 + p3;
                const int jl = mbase + ms * 16 + (lane >> 2);
                *(uint32_t*)(pst + jl * PST_ROWB + icl * 2)       = cvt_bf16x2(p1, p0);
                *(uint32_t*)(pst + (jl + 8) * PST_ROWB + icl * 2) = cvt_bf16x2(p3, p2);
            }
            #pragma unroll
            for (int off = 4; off <= 16; off <<= 1) {
                cs0 += __shfl_xor_sync(0xffffffffu, cs0, off);
                cs1 += __shfl_xor_sync(0xffffffffu, cs1, off);
            }
            if (lane < 4) {
                atomicAdd(lrow + i0 + icl, cs0);
                atomicAdd(lrow + i0 + icl + 1, cs1);
            }
        }
        __syncthreads();   // pst writes complete before coalesced read

        #pragma unroll
        for (int q = 0; q < 8; q++) {
            int id = q * 256 + t;
            int jl = id >> 4, w16 = id & 15;
            uint4 v = *(uint4*)(pst + jl * PST_ROWB + w16 * 16);
            *(uint4*)(ph + (size_t)(j0 + jl) * NPIX + i0 + w16 * 8) = v;
        }
        // trailing sync removed: next pst write happens only after the next
        // iteration's post-CPWAIT __syncthreads.
    }
}

// ============================================================================
// Kernel 2c: finalize.  invl = 1/l.
// ============================================================================
__global__ __launch_bounds__(256) void finalize_kernel()
{
    int idx = blockIdx.x * blockDim.x + threadIdx.x;
    if (idx < BATCH * NPIX) g_invl[idx] = 1.0f / g_l[idx];
}

// ============================================================================
// Kernel 3: output GEMM, fp16 mma, beta fused into A-path, BK=64
// (R14 core; f16x2 pack in convA).
// ============================================================================
#define ROWB2 144
#define G_OFF_A 0
#define G_OFF_B 18432
#define G_STAGE 55296
#define G_INVL (2 * G_STAGE)
#define GEMM_SMEM (G_INVL + NPIX * 4)

__global__ __launch_bounds__(512, 1) void out_gemm_mma(
    const float* __restrict__ x, const float* __restrict__ gamma,
    float* __restrict__ out)
{
    extern __shared__ char smem[];
    const uint32_t sb = smem_u32(smem);
    float* sinvl = (float*)(smem + G_INVL);

    const int b  = blockIdx.y;
    const int m0 = blockIdx.x * 128;
    const int t  = threadIdx.x;
    const int warp = t >> 5, lane = t & 31;
    const int wm = (warp & 3) * 32;
    const int wn = (warp >> 2) * 64;

    const __nv_bfloat16* pb = g_ph + (size_t)b * NPIX * NPIX;
    const __half* xh = g_xh16 + (size_t)b * CDIM * NPIX;
    const float* invl = g_invl + b * NPIX;

    float acc[2][8][4];
    #pragma unroll
    for (int i = 0; i < 2; i++)
        #pragma unroll
        for (int j = 0; j < 8; j++)
            #pragma unroll
            for (int q = 0; q < 4; q++) acc[i][j][q] = 0.f;

    const int a_row = lane & 15, a_k16 = (lane >> 4) << 4;
    const int b_row = (lane & 7) + ((lane >> 4) & 1) * 8;
    const int b_k16 = ((lane >> 3) & 1) * 16;

    const int NCH = NPIX / 64;

    const int ar0 = t >> 3, ag0 = t & 7;
    const int ar1 = (t + 512) >> 3, ag1 = (t + 512) & 7;

    auto convA = [&](uint4* areg, int i0, uint32_t st) {
        #pragma unroll
        for (int q = 0; q < 2; q++) {
            int r = q ? ar1 : ar0, g = q ? ag1 : ag0;
            const uint32_t* aw = (const uint32_t*)&areg[q];
            float iv[8];
            #pragma unroll
            for (int k = 0; k < 8; k++) iv[k] = sinvl[i0 + g * 8 + k];
            uint32_t w[4];
            #pragma unroll
            for (int p = 0; p < 4; p++) {
                float lo = __bfloat162float(__ushort_as_bfloat16((unsigned short)(aw[p] & 0xFFFF)));
                float hi = __bfloat162float(__ushort_as_bfloat16((unsigned short)(aw[p] >> 16)));
                w[p] = cvt_f16x2(hi * iv[p * 2 + 1], lo * iv[p * 2]);
            }
            *(uint4*)((char*)smem + (st - smem_u32(smem)) + r * ROWB2 + g * 16 + G_OFF_A) = *(uint4*)w;
        }
    };

    {
        int vi = t * 8;
        *(float4*)(sinvl + vi)     = *(const float4*)(invl + vi);
        *(float4*)(sinvl + vi + 4) = *(const float4*)(invl + vi + 4);
    }
    uint4 areg[2];
    areg[0] = *(const uint4*)(pb + (size_t)(m0 + ar0) * NPIX + ag0 * 8);
    areg[1] = *(const uint4*)(pb + (size_t)(m0 + ar1) * NPIX + ag1 * 8);
    {
        const uint32_t st = sb;
        #pragma unroll
        for (int q = 0; q < 4; q++) {
            int id = t + q * 512;
            int r = id >> 3, g = id & 7;
            CPASYNC16(st + r * ROWB2 + g * 16 + G_OFF_B, xh + (size_t)r * NPIX + g * 8);
        }
        CPCOMMIT();
    }
    __syncthreads();
    convA(areg, 0, sb);

    for (int kt = 0; kt < NCH; kt++) {
        const int s = kt & 1;
        const int i0n = (kt + 1) * 64;
        if (kt + 1 < NCH) {
            areg[0] = *(const uint4*)(pb + (size_t)(m0 + ar0) * NPIX + i0n + ag0 * 8);
            areg[1] = *(const uint4*)(pb + (size_t)(m0 + ar1) * NPIX + i0n + ag1 * 8);
            const uint32_t st = sb + (s ^ 1) * G_STAGE;
            #pragma unroll
            for (int q = 0; q < 4; q++) {
                int id = t + q * 512;
                int r = id >> 3, g = id & 7;
                CPASYNC16(st + r * ROWB2 + g * 16 + G_OFF_B, xh + (size_t)r * NPIX + i0n + g * 8);
            }
            CPCOMMIT();
            CPWAIT(1);
        } else {
            CPWAIT(0);
        }
        __syncthreads();

        const uint32_t st = sb + s * G_STAGE;
        #pragma unroll
        for (int ks = 0; ks < 4; ks++) {
            const int kB = ks * 32;
            uint32_t a_f[2][4];
            #pragma unroll
            for (int ms = 0; ms < 2; ms++) {
                uint32_t ra = st + (wm + ms * 16 + a_row) * ROWB2 + kB + a_k16;
                ldmx4(a_f[ms], ra + G_OFF_A);
            }
            #pragma unroll
            for (int np = 0; np < 4; np++) {
                uint32_t rb = st + (wn + np * 16 + b_row) * ROWB2 + kB + b_k16;
                uint32_t b_f[4];
                ldmx4(b_f, rb + G_OFF_B);
                #pragma unroll
                for (int ms = 0; ms < 2; ms++) {
                    #pragma unroll
                    for (int nh = 0; nh < 2; nh++) {
                        mma16816h(acc[ms][np * 2 + nh], a_f[ms], b_f + 2 * nh);
                    }
                }
            }
        }

        if (kt + 1 < NCH) {
            convA(areg, i0n, sb + (s ^ 1) * G_STAGE);
        }
        __syncthreads();
    }

    const float g = gamma[0];
    const float* xb = x   + (size_t)b * CDIM * NPIX;
    float*       ob = out + (size_t)b * CDIM * NPIX;
    const int jq = lane >> 2, cq = (lane & 3) * 2;

    #pragma unroll
    for (int ms = 0; ms < 2; ms++) {
        #pragma unroll
        for (int ni = 0; ni < 8; ni++) {
            int j = m0 + wm + ms * 16 + jq;
            int c = wn + ni * 8 + cq;
            float* a4 = acc[ms][ni];
            ob[(size_t)c * NPIX + j]            = xb[(size_t)c * NPIX + j]            + g * a4[0];
            ob[(size_t)(c + 1) * NPIX + j]      = xb[(size_t)(c + 1) * NPIX + j]      + g * a4[1];
            ob[(size_t)c * NPIX + j + 8]        = xb[(size_t)c * NPIX + j + 8]        + g * a4[2];
            ob[(size_t)(c + 1) * NPIX + j + 8]  = xb[(size_t)(c + 1) * NPIX + j + 8]  + g * a4[3];
        }
    }
}

// ============================================================================
extern "C" void kernel_launch(void* const* d_in, const int* in_sizes, int n_in,
                              void* d_out, int out_size)
{
    const float* x     = (const float*)d_in[0];
    const float* Wf    = (const float*)d_in[1];
    const float* bf    = (const float*)d_in[2];
    const float* Wg    = (const float*)d_in[3];
    const float* bg    = (const float*)d_in[4];
    const float* Wh    = (const float*)d_in[5];
    const float* bh    = (const float*)d_in[6];
    const float* gamma = (const float*)d_in[7];
    float* out = (float*)d_out;

    (void)in_sizes; (void)n_in; (void)out_size;

    cudaFuncSetAttribute(out_gemm_mma, cudaFuncAttributeMaxDynamicSharedMemorySize,
                         GEMM_SMEM);
    cudaFuncSetAttribute(score_kernel, cudaFuncAttributeMaxDynamicSharedMemorySize,
                         SCORE_SMEM);
    cudaFuncSetAttribute(proj_tc_kernel, cudaFuncAttributeMaxDynamicSharedMemorySize,
                         2 * PSTAGE);

    dim3 blk(256);
    setup_kernel<<<(BATCH * NPIX + CDIM * CDIM / 4 + 255) / 256, blk>>>(Wh);
    proj_fg_kernel<<<dim3(NPIX / 128, 1, BATCH), blk>>>(Wf, bf, Wg, bg, x);
    proj_tc_kernel<<<dim3(NPIX / 256, CDIM / 128, BATCH), 512, 2 * PSTAGE>>>(bh);
    score_kernel<<<dim3(NPIX / 128, BATCH), blk, SCORE_SMEM>>>();
    finalize_kernel<<<(BATCH * NPIX + 255) / 256, blk>>>();
    out_gemm_mma<<<dim3(NPIX / 128, BATCH), 512, GEMM_SMEM>>>(x, gamma, out);
}